// round 6
// baseline (speedup 1.0000x reference)
#include <cuda_runtime.h>

#define BATCH 8
#define HH 1024
#define WW 1024

#define TILE 104          // valid output span per tile dim
#define HALO 12           // >= 10 needed; 12 keeps float4 alignment
#define EXT  128          // TILE + 2*HALO
#define NWARP 16
#define RPW  8            // rows per warp (NWARP*RPW == EXT)
#define NT   512
#define NITER 10

// smem: u [(EXT+1) x EXT] (row EXT is a permanent zero row) + xq [NWARP x EXT]
#define SMEM_BYTES (((EXT + 1) * EXT + NWARP * EXT) * 4)

// sigmoid(2x) = 0.5*tanh(x) + 0.5  -> one MUFU
__device__ __forceinline__ float tanh_fast(float x) {
    float y;
    asm("tanh.approx.f32 %0, %1;" : "=f"(y) : "f"(x));
    return y;
}

__global__ void __launch_bounds__(NT, 1)
ccs_fused(const float* __restrict__ o, const float* __restrict__ vf,
          float* __restrict__ out) {
    extern __shared__ float sm[];
    float* su = sm;                        // u [(EXT+1)][EXT]
    float* xq = sm + (EXT + 1) * EXT;      // per-warp q bottom-row exchange [NWARP][EXT]

    const int tid  = threadIdx.x;
    const int w    = tid >> 5;
    const int lane = tid & 31;
    const int tx = blockIdx.x, ty = blockIdx.y, b = blockIdx.z;
    const int gi0 = ty * TILE - HALO;
    const int gj0 = tx * TILE - HALO;            // multiple of 4
    const int colbase = gj0 + lane * 4;          // global col of this lane's elem 0
    const int cb = min(max(colbase, 0), WW - 4); // clamped, 16B aligned
    const int er0 = w * RPW;
    const float* ob = o + (size_t)b * HH * WW;

    // ---- load vector field into REGISTERS (iteration-invariant), masked ----
    float4 v0[RPW], v1[RPW];
#pragma unroll
    for (int r = 0; r < RPW; r++) {
        int gr = gi0 + er0 + r;
        int grc = min(max(gr, 0), HH - 1);
        const float4* vfp = reinterpret_cast<const float4*>(vf + ((size_t)grc * WW + cb) * 2);
        float4 A = vfp[0];   // vf0[c], vf1[c], vf0[c+1], vf1[c+1]
        float4 B = vfp[1];
        float rm = ((unsigned)gr < HH) ? 1.f : 0.f;
        float m0 = rm * (((unsigned)(colbase + 0) < WW) ? 1.f : 0.f);
        float m1 = rm * (((unsigned)(colbase + 1) < WW) ? 1.f : 0.f);
        float m2 = rm * (((unsigned)(colbase + 2) < WW) ? 1.f : 0.f);
        float m3 = rm * (((unsigned)(colbase + 3) < WW) ? 1.f : 0.f);
        v0[r] = make_float4(A.x * m0, A.z * m1, B.x * m2, B.z * m3);
        v1[r] = make_float4(A.y * m0, A.w * m1, B.y * m2, B.w * m3);
    }

    // v1 of row er0-1 (up-neighbor for r=0), masked (row -1 -> zeros)
    float4 v1top;
    {
        int gr = gi0 + er0 - 1;
        int grc = min(max(gr, 0), HH - 1);
        const float4* vfp = reinterpret_cast<const float4*>(vf + ((size_t)grc * WW + cb) * 2);
        float4 A = vfp[0];
        float4 B = vfp[1];
        float rm = ((unsigned)gr < HH && er0 > 0) ? 1.f : 0.f;
        float m0 = rm * (((unsigned)(colbase + 0) < WW) ? 1.f : 0.f);
        float m1 = rm * (((unsigned)(colbase + 1) < WW) ? 1.f : 0.f);
        float m2 = rm * (((unsigned)(colbase + 2) < WW) ? 1.f : 0.f);
        float m3 = rm * (((unsigned)(colbase + 3) < WW) ? 1.f : 0.f);
        v1top = make_float4(A.y * m0, A.w * m1, B.y * m2, B.w * m3);
    }

    // ---- init: u = 0.5*tanh(o)+0.5 (masked) into smem, q = 0 in regs ----
    float4 q[RPW];
#pragma unroll
    for (int r = 0; r < RPW; r++) {
        int er = er0 + r;
        int gr = gi0 + er;
        int grc = min(max(gr, 0), HH - 1);
        float4 o4 = *reinterpret_cast<const float4*>(ob + (size_t)grc * WW + cb);
        float rm = ((unsigned)gr < HH) ? 1.f : 0.f;
        float m0 = rm * (((unsigned)(colbase + 0) < WW) ? 1.f : 0.f);
        float m1 = rm * (((unsigned)(colbase + 1) < WW) ? 1.f : 0.f);
        float m2 = rm * (((unsigned)(colbase + 2) < WW) ? 1.f : 0.f);
        float m3 = rm * (((unsigned)(colbase + 3) < WW) ? 1.f : 0.f);
        float4 u4;
        u4.x = m0 * fmaf(tanh_fast(o4.x), 0.5f, 0.5f);
        u4.y = m1 * fmaf(tanh_fast(o4.y), 0.5f, 0.5f);
        u4.z = m2 * fmaf(tanh_fast(o4.z), 0.5f, 0.5f);
        u4.w = m3 * fmaf(tanh_fast(o4.w), 0.5f, 0.5f);
        *reinterpret_cast<float4*>(&su[er * EXT + lane * 4]) = u4;
        q[r] = make_float4(0.f, 0.f, 0.f, 0.f);
    }
    // permanent zero row at er == EXT (down-neighbor of the last ext row)
    if (tid < EXT / 4)
        *reinterpret_cast<float4*>(&su[EXT * EXT + tid * 4]) = make_float4(0.f, 0.f, 0.f, 0.f);
    __syncthreads();

#pragma unroll 1
    for (int it = 0; it < NITER; it++) {
        const bool last = (it == NITER - 1);

        // ===== q-step: q = max(q - 0.5*((u_dn-u)*v1 + (u_rt-u)*v0), 0) =====
        // sliding window over smem u rows; out-of-image: vf==0 -> q stays 0
        {
            float4 cur = *reinterpret_cast<float4*>(&su[er0 * EXT + lane * 4]);
#pragma unroll
            for (int r = 0; r < RPW; r++) {
                float4 nxt = *reinterpret_cast<float4*>(&su[(er0 + r + 1) * EXT + lane * 4]);
                float ur = __shfl_down_sync(0xffffffffu, cur.x, 1);
                if (lane == 31) ur = 0.f;
                float t;
                t = (nxt.x - cur.x) * v1[r].x + (cur.y - cur.x) * v0[r].x;
                q[r].x = fmaxf(fmaf(-0.5f, t, q[r].x), 0.f);
                t = (nxt.y - cur.y) * v1[r].y + (cur.z - cur.y) * v0[r].y;
                q[r].y = fmaxf(fmaf(-0.5f, t, q[r].y), 0.f);
                t = (nxt.z - cur.z) * v1[r].z + (cur.w - cur.z) * v0[r].z;
                q[r].z = fmaxf(fmaf(-0.5f, t, q[r].z), 0.f);
                t = (nxt.w - cur.w) * v1[r].w + (ur - cur.w) * v0[r].w;
                q[r].w = fmaxf(fmaf(-0.5f, t, q[r].w), 0.f);
                cur = nxt;
            }
        }
        *reinterpret_cast<float4*>(&xq[w * EXT + lane * 4]) = q[RPW - 1];
        __syncthreads();

        // ===== u-step: Tq = div(vf*q); x = o - Tq; u = 0.5*tanh(x)+0.5 (or out=2x) =====
        {
            float4 qup;
            if (w > 0) qup = *reinterpret_cast<float4*>(&xq[(w - 1) * EXT + lane * 4]);
            else       qup = make_float4(0.f, 0.f, 0.f, 0.f);
            float4 v1p = v1top;
#pragma unroll
            for (int r = 0; r < RPW; r++) {
                int er = er0 + r;
                int gr = gi0 + er;
                int grc = min(max(gr, 0), HH - 1);
                float ql  = __shfl_up_sync(0xffffffffu, q[r].w, 1);
                float v0l = __shfl_up_sync(0xffffffffu, v0[r].w, 1);
                if (lane == 0) { ql = 0.f; v0l = 0.f; }
                float4 o4 = *reinterpret_cast<const float4*>(ob + (size_t)grc * WW + cb);

                float Tq0 = v1[r].x * q[r].x - v1p.x * qup.x + v0[r].x * q[r].x - v0l      * ql;
                float Tq1 = v1[r].y * q[r].y - v1p.y * qup.y + v0[r].y * q[r].y - v0[r].x * q[r].x;
                float Tq2 = v1[r].z * q[r].z - v1p.z * qup.z + v0[r].z * q[r].z - v0[r].y * q[r].y;
                float Tq3 = v1[r].w * q[r].w - v1p.w * qup.w + v0[r].w * q[r].w - v0[r].z * q[r].z;
                float x0 = o4.x - Tq0;
                float x1 = o4.y - Tq1;
                float x2 = o4.z - Tq2;
                float x3 = o4.w - Tq3;

                if (!last) {
                    float rm = ((unsigned)gr < HH) ? 1.f : 0.f;
                    float m0 = rm * (((unsigned)(colbase + 0) < WW) ? 1.f : 0.f);
                    float m1 = rm * (((unsigned)(colbase + 1) < WW) ? 1.f : 0.f);
                    float m2 = rm * (((unsigned)(colbase + 2) < WW) ? 1.f : 0.f);
                    float m3 = rm * (((unsigned)(colbase + 3) < WW) ? 1.f : 0.f);
                    float4 u4;
                    u4.x = m0 * fmaf(tanh_fast(x0), 0.5f, 0.5f);
                    u4.y = m1 * fmaf(tanh_fast(x1), 0.5f, 0.5f);
                    u4.z = m2 * fmaf(tanh_fast(x2), 0.5f, 0.5f);
                    u4.w = m3 * fmaf(tanh_fast(x3), 0.5f, 0.5f);
                    *reinterpret_cast<float4*>(&su[er * EXT + lane * 4]) = u4;
                } else {
                    // final: out = (o - Tq)/EPS = 2*x, only the tile's valid center
                    if (er >= HALO && er < HALO + TILE && gr < HH &&
                        lane >= HALO / 4 && lane < (HALO + TILE) / 4 && colbase < WW) {
                        *reinterpret_cast<float4*>(out + (size_t)((b * HH + gr) * WW + colbase)) =
                            make_float4(2.f * x0, 2.f * x1, 2.f * x2, 2.f * x3);
                    }
                }
                v1p = v1[r];
                qup = q[r];
            }
        }
        __syncthreads();
    }
}

extern "C" void kernel_launch(void* const* d_in, const int* in_sizes, int n_in,
                              void* d_out, int out_size) {
    const float* o  = (const float*)d_in[0];
    const float* vf = (const float*)d_in[1];
    float* out = (float*)d_out;

    static bool attr_set = false;
    if (!attr_set) {
        cudaFuncSetAttribute(ccs_fused, cudaFuncAttributeMaxDynamicSharedMemorySize,
                             SMEM_BYTES);
        attr_set = true;
    }

    dim3 grid((WW + TILE - 1) / TILE, (HH + TILE - 1) / TILE, BATCH);  // 10 x 10 x 8
    ccs_fused<<<grid, NT, SMEM_BYTES>>>(o, vf, out);
}